// round 14
// baseline (speedup 1.0000x reference)
#include <cuda_runtime.h>
#include <cstdint>

#define N_NODES 50000
#define E_EDGES 800000
#define IN_DIM  128
#define HEADS   4
#define OUT_DIM 32
#define C_DIM   128   // HEADS*OUT_DIM
#define NEG_SLOPE 0.2f
#define EPS_F 1e-16f
#define NEG_INF_F -3.402823e38f

#define SB 256
#define NB ((N_NODES + SB - 1) / SB)   // 196 scan blocks

// ---------------- scratch (device globals; no runtime allocation) ----------------
__device__ __align__(16) float g_h[N_NODES * C_DIM];      // 25.6 MB: h = x @ W^T
__device__ __align__(16) float g_asrc[N_NODES * HEADS];   // per-node src scores
__device__ __align__(16) float g_adst[N_NODES * HEADS];   // per-node dst scores
__device__ __align__(16) int   g_cnt[N_NODES];            // dst histogram (zeroed by scan)
__device__ __align__(16) int   g_rank[E_EDGES];           // edge rank within its dst bucket
__device__ __align__(16) int   g_rowstart[N_NODES + 1];   // CSR row offsets
__device__ __align__(16) unsigned long long g_state[NB];  // lookback state (zeroed by hist)
__device__ __align__(16) int2  g_bucket[E_EDGES];         // per-dst edge list: (src, edge_id)

// ================= K1: tf32 mma.sync GEMM + per-node attention scores =================
// block = 128-row M tile, 256 threads (8 warps, warp owns 16 rows x 128 cols)
#define GP 132   // smem pitch in words (128+4: quad LDS pattern conflict-free)
#define GEMM_SMEM_WORDS (2 * 128 * GP + 256)
#define GEMM_SMEM_BYTES (GEMM_SMEM_WORDS * 4)

__device__ __forceinline__ uint32_t f2tf32(float f) {
    uint32_t r;
    asm("cvt.rna.tf32.f32 %0, %1;" : "=r"(r) : "f"(f));
    return r;
}
__device__ __forceinline__ void mma_tf32(float d[4], uint32_t a0, uint32_t a1,
                                         uint32_t a2, uint32_t a3,
                                         uint32_t b0, uint32_t b1) {
    asm volatile(
        "mma.sync.aligned.m16n8k8.row.col.f32.tf32.tf32.f32 "
        "{%0,%1,%2,%3}, {%4,%5,%6,%7}, {%8,%9}, {%0,%1,%2,%3};"
        : "+f"(d[0]), "+f"(d[1]), "+f"(d[2]), "+f"(d[3])
        : "r"(a0), "r"(a1), "r"(a2), "r"(a3), "r"(b0), "r"(b1));
}

__global__ __launch_bounds__(256, 1) void gemm_mma_kernel(const float* __restrict__ x,
                                                          const float* __restrict__ W,
                                                          const float* __restrict__ att_src,
                                                          const float* __restrict__ att_dst) {
    extern __shared__ uint32_t smem[];
    uint32_t* xs    = smem;                 // [128][GP] tf32 bits
    uint32_t* ws    = smem + 128 * GP;      // [128][GP] tf32 bits
    float*    s_att = (float*)(smem + 2 * 128 * GP);   // [256] = att_src | att_dst

    const int tid  = threadIdx.x;
    const int wid  = tid >> 5;
    const int lane = tid & 31;
    const int row0 = blockIdx.x * 128;

    s_att[tid] = (tid < 128) ? att_src[tid] : att_dst[tid - 128];

    // load + convert W and x tile to tf32 smem (float4 granularity)
    for (int idx = tid; idx < 4096; idx += 256) {
        int r = idx >> 5, q = idx & 31;
        float4 wv = *(const float4*)&W[r * IN_DIM + q * 4];
        uint32_t* wp = &ws[r * GP + q * 4];
        wp[0] = f2tf32(wv.x); wp[1] = f2tf32(wv.y);
        wp[2] = f2tf32(wv.z); wp[3] = f2tf32(wv.w);

        int m = row0 + r;
        float4 xv = make_float4(0.f, 0.f, 0.f, 0.f);
        if (m < N_NODES) xv = *(const float4*)&x[m * IN_DIM + q * 4];
        uint32_t* xp = &xs[r * GP + q * 4];
        xp[0] = f2tf32(xv.x); xp[1] = f2tf32(xv.y);
        xp[2] = f2tf32(xv.z); xp[3] = f2tf32(xv.w);
    }
    __syncthreads();

    const int g  = lane >> 2;   // group id (row within fragment)
    const int t4 = lane & 3;

    float acc[16][4];
#pragma unroll
    for (int n = 0; n < 16; n++)
#pragma unroll
        for (int j = 0; j < 4; j++) acc[n][j] = 0.0f;

    const int arow = wid * 16 + g;
#pragma unroll 1
    for (int ks = 0; ks < 16; ks++) {
        int kc = ks * 8 + t4;
        uint32_t a0 = xs[arow * GP + kc];
        uint32_t a1 = xs[(arow + 8) * GP + kc];
        uint32_t a2 = xs[arow * GP + kc + 4];
        uint32_t a3 = xs[(arow + 8) * GP + kc + 4];
#pragma unroll
        for (int n = 0; n < 16; n++) {
            uint32_t b0 = ws[(n * 8 + g) * GP + kc];
            uint32_t b1 = ws[(n * 8 + g) * GP + kc + 4];
            mma_tf32(acc[n], a0, a1, a2, a3, b0, b1);
        }
    }

    // epilogue: store h rows r0 & r1, fold attention dot products
    const int r0 = row0 + wid * 16 + g;
    const int r1 = r0 + 8;
    float vs0[HEADS], vd0[HEADS], vs1[HEADS], vd1[HEADS];
#pragma unroll
    for (int h = 0; h < HEADS; h++) { vs0[h] = vd0[h] = vs1[h] = vd1[h] = 0.f; }

#pragma unroll
    for (int n = 0; n < 16; n++) {
        int c0 = n * 8 + t4 * 2;
        int c1 = c0 + 1;
        int h  = n >> 2;   // head = c0 >> 5
        if (r0 < N_NODES)
            *(float2*)&g_h[(size_t)r0 * C_DIM + c0] = make_float2(acc[n][0], acc[n][1]);
        if (r1 < N_NODES)
            *(float2*)&g_h[(size_t)r1 * C_DIM + c0] = make_float2(acc[n][2], acc[n][3]);
        vs0[h] += acc[n][0] * s_att[c0]       + acc[n][1] * s_att[c1];
        vd0[h] += acc[n][0] * s_att[128 + c0] + acc[n][1] * s_att[128 + c1];
        vs1[h] += acc[n][2] * s_att[c0]       + acc[n][3] * s_att[c1];
        vd1[h] += acc[n][2] * s_att[128 + c0] + acc[n][3] * s_att[128 + c1];
    }
#pragma unroll
    for (int h = 0; h < HEADS; h++) {
        vs0[h] += __shfl_xor_sync(0xffffffffu, vs0[h], 1);
        vs0[h] += __shfl_xor_sync(0xffffffffu, vs0[h], 2);
        vd0[h] += __shfl_xor_sync(0xffffffffu, vd0[h], 1);
        vd0[h] += __shfl_xor_sync(0xffffffffu, vd0[h], 2);
        vs1[h] += __shfl_xor_sync(0xffffffffu, vs1[h], 1);
        vs1[h] += __shfl_xor_sync(0xffffffffu, vs1[h], 2);
        vd1[h] += __shfl_xor_sync(0xffffffffu, vd1[h], 1);
        vd1[h] += __shfl_xor_sync(0xffffffffu, vd1[h], 2);
    }
    if (t4 == 0) {
        if (r0 < N_NODES) {
#pragma unroll
            for (int h = 0; h < HEADS; h++) {
                g_asrc[r0 * HEADS + h] = vs0[h];
                g_adst[r0 * HEADS + h] = vd0[h];
            }
        }
        if (r1 < N_NODES) {
#pragma unroll
            for (int h = 0; h < HEADS; h++) {
                g_asrc[r1 * HEADS + h] = vs1[h];
                g_adst[r1 * HEADS + h] = vd1[h];
            }
        }
    }
}

// ---------------- K2: dst histogram + per-edge rank (+ zero lookback state) ----------------
__global__ void hist_kernel(const int* __restrict__ ei) {
    if (threadIdx.x == 0 && blockIdx.x < NB) g_state[blockIdx.x] = 0ULL;
    int e = blockIdx.x * blockDim.x + threadIdx.x;
    if (e >= E_EDGES) return;
    g_rank[e] = atomicAdd(&g_cnt[ei[E_EDGES + e]], 1);
}

// ---------------- K3: single-pass exclusive scan (decoupled lookback) ----------------
// g_state[b]: (flag<<32)|value; flag 0=empty, 1=aggregate, 2=inclusive prefix
__global__ void scan_kernel() {
    __shared__ int sh[SB];
    __shared__ int s_prefix;
    const int t   = threadIdx.x;
    const int bid = blockIdx.x;
    const int i   = bid * SB + t;

    int v = (i < N_NODES) ? g_cnt[i] : 0;
    if (i < N_NODES) g_cnt[i] = 0;      // reset for next graph replay

    sh[t] = v;
    __syncthreads();
#pragma unroll
    for (int off = 1; off < SB; off <<= 1) {
        int u = (t >= off) ? sh[t - off] : 0;
        __syncthreads();
        sh[t] += u;
        __syncthreads();
    }
    const int incl  = sh[t];
    const int total = sh[SB - 1];

    if (t == 0) {
        if (bid == 0) {
            atomicExch(&g_state[0], (2ULL << 32) | (unsigned)total);
            s_prefix = 0;
        } else {
            atomicExch(&g_state[bid], (1ULL << 32) | (unsigned)total);
            int prefix = 0;
            int j = bid - 1;
            while (j >= 0) {
                unsigned long long st = *((volatile unsigned long long*)&g_state[j]);
                unsigned flag = (unsigned)(st >> 32);
                if (flag == 2u)      { prefix += (int)(unsigned)st; break; }
                else if (flag == 1u) { prefix += (int)(unsigned)st; j--; }
                // flag==0: spin
            }
            atomicExch(&g_state[bid], (2ULL << 32) | (unsigned)(prefix + total));
            s_prefix = prefix;
        }
    }
    __syncthreads();

    const int excl = s_prefix + incl - v;
    if (i < N_NODES) g_rowstart[i] = excl;
    if (i == N_NODES - 1) g_rowstart[N_NODES] = excl + v;
}

// ---------------- K4: fill CSR buckets (atomic-free) ----------------
__global__ void fill_kernel(const int* __restrict__ ei) {
    int e = blockIdx.x * blockDim.x + threadIdx.x;
    if (e >= E_EDGES) return;
    int src = ei[e];
    int dst = ei[E_EDGES + e];
    g_bucket[g_rowstart[dst] + g_rank[e]] = make_int2(src, e);
}

// ---------------- K5: warp-per-node gather — softmax + aggregation, atomic-free --------
__device__ __forceinline__ float4 edge_alpha(int src, float4 ad) {
    float4 as = *(const float4*)&g_asrc[src * HEADS];
    float4 a;
    a.x = as.x + ad.x; a.x = fmaxf(a.x, NEG_SLOPE * a.x);
    a.y = as.y + ad.y; a.y = fmaxf(a.y, NEG_SLOPE * a.y);
    a.z = as.z + ad.z; a.z = fmaxf(a.z, NEG_SLOPE * a.z);
    a.w = as.w + ad.w; a.w = fmaxf(a.w, NEG_SLOPE * a.w);
    return a;
}

#define GW 8   // warps per block
__global__ void gather_kernel(const float* __restrict__ bias,
                              float* __restrict__ out,
                              float* __restrict__ alpha_out) {
    __shared__ float4 s_al[GW][32];
    __shared__ int    s_src[GW][32];

    const int lane = threadIdx.x & 31;
    const int w    = threadIdx.x >> 5;
    const int node = blockIdx.x * GW + w;
    if (node >= N_NODES) return;

    const int start = g_rowstart[node];
    const int end   = g_rowstart[node + 1];
    const int deg   = end - start;
    const int head  = lane >> 3;

    float4 acc = *(const float4*)&bias[lane * 4];

#define ACCUM_CHUNK(cnt)                                                          \
    do {                                                                          \
        int j = 0;                                                                \
        for (; j + 4 <= (cnt); j += 4) {                                          \
            int   s0 = s_src[w][j+0], s1 = s_src[w][j+1];                         \
            int   s2 = s_src[w][j+2], s3 = s_src[w][j+3];                         \
            float a0 = ((const float*)&s_al[w][j+0])[head];                       \
            float a1 = ((const float*)&s_al[w][j+1])[head];                       \
            float a2 = ((const float*)&s_al[w][j+2])[head];                       \
            float a3 = ((const float*)&s_al[w][j+3])[head];                       \
            float4 h0 = *(const float4*)&g_h[s0 * C_DIM + lane * 4];              \
            float4 h1 = *(const float4*)&g_h[s1 * C_DIM + lane * 4];              \
            float4 h2 = *(const float4*)&g_h[s2 * C_DIM + lane * 4];              \
            float4 h3 = *(const float4*)&g_h[s3 * C_DIM + lane * 4];              \
            acc.x = fmaf(h0.x, a0, acc.x); acc.y = fmaf(h0.y, a0, acc.y);         \
            acc.z = fmaf(h0.z, a0, acc.z); acc.w = fmaf(h0.w, a0, acc.w);         \
            acc.x = fmaf(h1.x, a1, acc.x); acc.y = fmaf(h1.y, a1, acc.y);         \
            acc.z = fmaf(h1.z, a1, acc.z); acc.w = fmaf(h1.w, a1, acc.w);         \
            acc.x = fmaf(h2.x, a2, acc.x); acc.y = fmaf(h2.y, a2, acc.y);         \
            acc.z = fmaf(h2.z, a2, acc.z); acc.w = fmaf(h2.w, a2, acc.w);         \
            acc.x = fmaf(h3.x, a3, acc.x); acc.y = fmaf(h3.y, a3, acc.y);         \
            acc.z = fmaf(h3.z, a3, acc.z); acc.w = fmaf(h3.w, a3, acc.w);         \
        }                                                                         \
        for (; j < (cnt); j++) {                                                  \
            int   sj = s_src[w][j];                                               \
            float aj = ((const float*)&s_al[w][j])[head];                         \
            float4 hv = *(const float4*)&g_h[sj * C_DIM + lane * 4];              \
            acc.x = fmaf(hv.x, aj, acc.x); acc.y = fmaf(hv.y, aj, acc.y);         \
            acc.z = fmaf(hv.z, aj, acc.z); acc.w = fmaf(hv.w, aj, acc.w);         \
        }                                                                         \
    } while (0)

    if (deg > 0 && deg <= 32) {
        float4 ad = *(const float4*)&g_adst[node * HEADS];
        int idx = start + lane;
        bool valid = idx < end;
        int2 be = make_int2(0, 0);
        float4 a = make_float4(NEG_INF_F, NEG_INF_F, NEG_INF_F, NEG_INF_F);
        if (valid) {
            be = g_bucket[idx];
            a = edge_alpha(be.x, ad);
        }
        float4 m = a;
#pragma unroll
        for (int off = 16; off; off >>= 1) {
            m.x = fmaxf(m.x, __shfl_xor_sync(0xffffffffu, m.x, off));
            m.y = fmaxf(m.y, __shfl_xor_sync(0xffffffffu, m.y, off));
            m.z = fmaxf(m.z, __shfl_xor_sync(0xffffffffu, m.z, off));
            m.w = fmaxf(m.w, __shfl_xor_sync(0xffffffffu, m.w, off));
        }
        float4 e = make_float4(0.f, 0.f, 0.f, 0.f);
        if (valid) {
            e.x = __expf(a.x - m.x); e.y = __expf(a.y - m.y);
            e.z = __expf(a.z - m.z); e.w = __expf(a.w - m.w);
        }
        float4 s = e;
#pragma unroll
        for (int off = 16; off; off >>= 1) {
            s.x += __shfl_xor_sync(0xffffffffu, s.x, off);
            s.y += __shfl_xor_sync(0xffffffffu, s.y, off);
            s.z += __shfl_xor_sync(0xffffffffu, s.z, off);
            s.w += __shfl_xor_sync(0xffffffffu, s.w, off);
        }
        float4 al;
        al.x = e.x / (s.x + EPS_F); al.y = e.y / (s.y + EPS_F);
        al.z = e.z / (s.z + EPS_F); al.w = e.w / (s.w + EPS_F);
        if (valid) {
            alpha_out[be.y] = 0.25f * (al.x + al.y + al.z + al.w);
            s_al[w][lane]  = al;
            s_src[w][lane] = be.x;
        }
        __syncwarp();
        ACCUM_CHUNK(deg);
    } else if (deg > 32) {
        float4 ad = *(const float4*)&g_adst[node * HEADS];
        float4 m = make_float4(NEG_INF_F, NEG_INF_F, NEG_INF_F, NEG_INF_F);
        float4 s = make_float4(0.f, 0.f, 0.f, 0.f);
        for (int idx = start + lane; idx < end; idx += 32) {
            int2 be = g_bucket[idx];
            float4 a = edge_alpha(be.x, ad);
            float4 nm;
            nm.x = fmaxf(m.x, a.x); nm.y = fmaxf(m.y, a.y);
            nm.z = fmaxf(m.z, a.z); nm.w = fmaxf(m.w, a.w);
            s.x = s.x * __expf(m.x - nm.x) + __expf(a.x - nm.x);
            s.y = s.y * __expf(m.y - nm.y) + __expf(a.y - nm.y);
            s.z = s.z * __expf(m.z - nm.z) + __expf(a.z - nm.z);
            s.w = s.w * __expf(m.w - nm.w) + __expf(a.w - nm.w);
            m = nm;
        }
#pragma unroll
        for (int off = 16; off; off >>= 1) {
            float4 mo, so;
            mo.x = __shfl_xor_sync(0xffffffffu, m.x, off);
            mo.y = __shfl_xor_sync(0xffffffffu, m.y, off);
            mo.z = __shfl_xor_sync(0xffffffffu, m.z, off);
            mo.w = __shfl_xor_sync(0xffffffffu, m.w, off);
            so.x = __shfl_xor_sync(0xffffffffu, s.x, off);
            so.y = __shfl_xor_sync(0xffffffffu, s.y, off);
            so.z = __shfl_xor_sync(0xffffffffu, s.z, off);
            so.w = __shfl_xor_sync(0xffffffffu, s.w, off);
            float4 nm;
            nm.x = fmaxf(m.x, mo.x); nm.y = fmaxf(m.y, mo.y);
            nm.z = fmaxf(m.z, mo.z); nm.w = fmaxf(m.w, mo.w);
            s.x = s.x * __expf(m.x - nm.x) + so.x * __expf(mo.x - nm.x);
            s.y = s.y * __expf(m.y - nm.y) + so.y * __expf(mo.y - nm.y);
            s.z = s.z * __expf(m.z - nm.z) + so.z * __expf(mo.z - nm.z);
            s.w = s.w * __expf(m.w - nm.w) + so.w * __expf(mo.w - nm.w);
            m = nm;
        }
        float4 inv;
        inv.x = 1.0f / (s.x + EPS_F); inv.y = 1.0f / (s.y + EPS_F);
        inv.z = 1.0f / (s.z + EPS_F); inv.w = 1.0f / (s.w + EPS_F);

        for (int base = start; base < end; base += 32) {
            int idx = base + lane;
            if (idx < end) {
                int2 be = g_bucket[idx];
                float4 a = edge_alpha(be.x, ad);
                float4 al;
                al.x = __expf(a.x - m.x) * inv.x;
                al.y = __expf(a.y - m.y) * inv.y;
                al.z = __expf(a.z - m.z) * inv.z;
                al.w = __expf(a.w - m.w) * inv.w;
                alpha_out[be.y] = 0.25f * (al.x + al.y + al.z + al.w);
                s_al[w][lane]  = al;
                s_src[w][lane] = be.x;
            }
            __syncwarp();
            int cnt = min(32, end - base);
            ACCUM_CHUNK(cnt);
            __syncwarp();
        }
    }

    *(float4*)&out[node * C_DIM + lane * 4] = acc;
#undef ACCUM_CHUNK
}

// ---------------- launch ----------------
extern "C" void kernel_launch(void* const* d_in, const int* in_sizes, int n_in,
                              void* d_out, int out_size) {
    const float* x       = (const float*)d_in[0];
    const int*   ei      = (const int*)d_in[1];     // edge_index is int32
    const float* W       = (const float*)d_in[2];
    const float* att_src = (const float*)d_in[3];
    const float* att_dst = (const float*)d_in[4];
    const float* bias    = (const float*)d_in[5];
    (void)in_sizes; (void)n_in; (void)out_size;

    float* out       = (float*)d_out;
    float* alpha_out = out + (size_t)N_NODES * C_DIM;

    cudaFuncSetAttribute(gemm_mma_kernel,
                         cudaFuncAttributeMaxDynamicSharedMemorySize, GEMM_SMEM_BYTES);

    gemm_mma_kernel<<<(N_NODES + 127) / 128, 256, GEMM_SMEM_BYTES>>>(x, W, att_src, att_dst);
    hist_kernel<<<(E_EDGES + 255) / 256, 256>>>(ei);
    scan_kernel<<<NB, SB>>>();
    fill_kernel<<<(E_EDGES + 255) / 256, 256>>>(ei);
    gather_kernel<<<(N_NODES + GW - 1) / GW, GW * 32>>>(bias, out, alpha_out);
}

// round 15
// speedup vs baseline: 1.0225x; 1.0225x over previous
#include <cuda_runtime.h>
#include <cstdint>

#define N_NODES 50000
#define E_EDGES 800000
#define IN_DIM  128
#define HEADS   4
#define OUT_DIM 32
#define C_DIM   128   // HEADS*OUT_DIM
#define NEG_SLOPE 0.2f
#define EPS_F 1e-16f
#define NEG_INF_F -3.402823e38f

#define SB 256
#define NB ((N_NODES + SB - 1) / SB)   // 196 scan blocks

#define GEMM_BLOCKS ((N_NODES + 127) / 128)          // 391
#define HIST_THREADS ((E_EDGES + 3) / 4)             // 200000 (4 edges/thread)
#define HIST_BLOCKS ((HIST_THREADS + 255) / 256)     // 782
#define HIST_STRIDE (HIST_BLOCKS * 256)              // 200192

// ---------------- scratch (device globals; no runtime allocation) ----------------
__device__ __align__(16) float g_h[N_NODES * C_DIM];      // 25.6 MB: h = x @ W^T
__device__ __align__(16) float g_asrc[N_NODES * HEADS];   // per-node src scores
__device__ __align__(16) float g_adst[N_NODES * HEADS];   // per-node dst scores
__device__ __align__(16) int   g_cnt[N_NODES];            // dst histogram (zeroed by scan3)
__device__ __align__(16) int   g_rank[E_EDGES];           // edge rank within its dst bucket
__device__ __align__(16) int   g_rowstart[N_NODES + 1];   // CSR row offsets
__device__ __align__(16) int   g_bsum[NB];                // scan block sums
__device__ __align__(16) int2  g_bucket[E_EDGES];         // per-dst edge list: (src, edge_id)

// ================= K1: fused [tf32 mma GEMM + attention scores] | [dst histogram] ======
#define GP 132   // smem pitch in words (128+4: quad LDS pattern conflict-free)
#define GEMM_SMEM_WORDS (2 * 128 * GP + 256)
#define GEMM_SMEM_BYTES (GEMM_SMEM_WORDS * 4)

__device__ __forceinline__ uint32_t f2tf32(float f) {
    uint32_t r;
    asm("cvt.rna.tf32.f32 %0, %1;" : "=r"(r) : "f"(f));
    return r;
}
__device__ __forceinline__ void mma_tf32(float d[4], uint32_t a0, uint32_t a1,
                                         uint32_t a2, uint32_t a3,
                                         uint32_t b0, uint32_t b1) {
    asm volatile(
        "mma.sync.aligned.m16n8k8.row.col.f32.tf32.tf32.f32 "
        "{%0,%1,%2,%3}, {%4,%5,%6,%7}, {%8,%9}, {%0,%1,%2,%3};"
        : "+f"(d[0]), "+f"(d[1]), "+f"(d[2]), "+f"(d[3])
        : "r"(a0), "r"(a1), "r"(a2), "r"(a3), "r"(b0), "r"(b1));
}

__global__ __launch_bounds__(256, 1) void gemm_hist_kernel(const float* __restrict__ x,
                                                           const float* __restrict__ W,
                                                           const float* __restrict__ att_src,
                                                           const float* __restrict__ att_dst,
                                                           const int* __restrict__ ei) {
    // -------- histogram blocks (pack into GEMM's last-wave bubble) --------
    if (blockIdx.x >= GEMM_BLOCKS) {
        int tbase = (blockIdx.x - GEMM_BLOCKS) * 256 + threadIdx.x;
        // 4 independent gather->atomic chains per thread (MLP=4), batches coalesced
        int e0 = tbase;
        int e1 = tbase + HIST_STRIDE;
        int e2 = tbase + 2 * HIST_STRIDE;
        int e3 = tbase + 3 * HIST_STRIDE;
        int d0 = (e0 < E_EDGES) ? ei[E_EDGES + e0] : 0;
        int d1 = (e1 < E_EDGES) ? ei[E_EDGES + e1] : 0;
        int d2 = (e2 < E_EDGES) ? ei[E_EDGES + e2] : 0;
        int d3 = (e3 < E_EDGES) ? ei[E_EDGES + e3] : 0;
        if (e0 < E_EDGES) g_rank[e0] = atomicAdd(&g_cnt[d0], 1);
        if (e1 < E_EDGES) g_rank[e1] = atomicAdd(&g_cnt[d1], 1);
        if (e2 < E_EDGES) g_rank[e2] = atomicAdd(&g_cnt[d2], 1);
        if (e3 < E_EDGES) g_rank[e3] = atomicAdd(&g_cnt[d3], 1);
        return;
    }

    // -------- GEMM blocks --------
    extern __shared__ uint32_t smem[];
    uint32_t* xs    = smem;                 // [128][GP] tf32 bits
    uint32_t* ws    = smem + 128 * GP;      // [128][GP] tf32 bits
    float*    s_att = (float*)(smem + 2 * 128 * GP);   // [256] = att_src | att_dst

    const int tid  = threadIdx.x;
    const int wid  = tid >> 5;
    const int lane = tid & 31;
    const int row0 = blockIdx.x * 128;

    s_att[tid] = (tid < 128) ? att_src[tid] : att_dst[tid - 128];

    for (int idx = tid; idx < 4096; idx += 256) {
        int r = idx >> 5, q = idx & 31;
        float4 wv = *(const float4*)&W[r * IN_DIM + q * 4];
        uint32_t* wp = &ws[r * GP + q * 4];
        wp[0] = f2tf32(wv.x); wp[1] = f2tf32(wv.y);
        wp[2] = f2tf32(wv.z); wp[3] = f2tf32(wv.w);

        int m = row0 + r;
        float4 xv = make_float4(0.f, 0.f, 0.f, 0.f);
        if (m < N_NODES) xv = *(const float4*)&x[m * IN_DIM + q * 4];
        uint32_t* xp = &xs[r * GP + q * 4];
        xp[0] = f2tf32(xv.x); xp[1] = f2tf32(xv.y);
        xp[2] = f2tf32(xv.z); xp[3] = f2tf32(xv.w);
    }
    __syncthreads();

    const int g  = lane >> 2;   // group id (row within fragment)
    const int t4 = lane & 3;

    float acc[16][4];
#pragma unroll
    for (int n = 0; n < 16; n++)
#pragma unroll
        for (int j = 0; j < 4; j++) acc[n][j] = 0.0f;

    const int arow = wid * 16 + g;
#pragma unroll 1
    for (int ks = 0; ks < 16; ks++) {
        int kc = ks * 8 + t4;
        uint32_t a0 = xs[arow * GP + kc];
        uint32_t a1 = xs[(arow + 8) * GP + kc];
        uint32_t a2 = xs[arow * GP + kc + 4];
        uint32_t a3 = xs[(arow + 8) * GP + kc + 4];
#pragma unroll
        for (int n = 0; n < 16; n++) {
            uint32_t b0 = ws[(n * 8 + g) * GP + kc];
            uint32_t b1 = ws[(n * 8 + g) * GP + kc + 4];
            mma_tf32(acc[n], a0, a1, a2, a3, b0, b1);
        }
    }

    // epilogue: store h rows r0 & r1, fold attention dot products
    const int r0 = row0 + wid * 16 + g;
    const int r1 = r0 + 8;
    float vs0[HEADS], vd0[HEADS], vs1[HEADS], vd1[HEADS];
#pragma unroll
    for (int h = 0; h < HEADS; h++) { vs0[h] = vd0[h] = vs1[h] = vd1[h] = 0.f; }

#pragma unroll
    for (int n = 0; n < 16; n++) {
        int c0 = n * 8 + t4 * 2;
        int c1 = c0 + 1;
        int h  = n >> 2;   // head = c0 >> 5
        if (r0 < N_NODES)
            *(float2*)&g_h[(size_t)r0 * C_DIM + c0] = make_float2(acc[n][0], acc[n][1]);
        if (r1 < N_NODES)
            *(float2*)&g_h[(size_t)r1 * C_DIM + c0] = make_float2(acc[n][2], acc[n][3]);
        vs0[h] += acc[n][0] * s_att[c0]       + acc[n][1] * s_att[c1];
        vd0[h] += acc[n][0] * s_att[128 + c0] + acc[n][1] * s_att[128 + c1];
        vs1[h] += acc[n][2] * s_att[c0]       + acc[n][3] * s_att[c1];
        vd1[h] += acc[n][2] * s_att[128 + c0] + acc[n][3] * s_att[128 + c1];
    }
#pragma unroll
    for (int h = 0; h < HEADS; h++) {
        vs0[h] += __shfl_xor_sync(0xffffffffu, vs0[h], 1);
        vs0[h] += __shfl_xor_sync(0xffffffffu, vs0[h], 2);
        vd0[h] += __shfl_xor_sync(0xffffffffu, vd0[h], 1);
        vd0[h] += __shfl_xor_sync(0xffffffffu, vd0[h], 2);
        vs1[h] += __shfl_xor_sync(0xffffffffu, vs1[h], 1);
        vs1[h] += __shfl_xor_sync(0xffffffffu, vs1[h], 2);
        vd1[h] += __shfl_xor_sync(0xffffffffu, vd1[h], 1);
        vd1[h] += __shfl_xor_sync(0xffffffffu, vd1[h], 2);
    }
    if (t4 == 0) {
        if (r0 < N_NODES) {
#pragma unroll
            for (int h = 0; h < HEADS; h++) {
                g_asrc[r0 * HEADS + h] = vs0[h];
                g_adst[r0 * HEADS + h] = vd0[h];
            }
        }
        if (r1 < N_NODES) {
#pragma unroll
            for (int h = 0; h < HEADS; h++) {
                g_asrc[r1 * HEADS + h] = vs1[h];
                g_adst[r1 * HEADS + h] = vd1[h];
            }
        }
    }
}

// ---------------- K3a/b/c: parallel exclusive scan of g_cnt -> g_rowstart ----------------
__global__ void scan1_kernel() {
    __shared__ int sh[SB];
    int t = threadIdx.x;
    int i = blockIdx.x * SB + t;
    sh[t] = (i < N_NODES) ? g_cnt[i] : 0;
    __syncthreads();
#pragma unroll
    for (int off = SB / 2; off; off >>= 1) {
        if (t < off) sh[t] += sh[t + off];
        __syncthreads();
    }
    if (t == 0) g_bsum[blockIdx.x] = sh[0];
}

__global__ void scan2_kernel() {
    __shared__ int sh[SB];
    int t = threadIdx.x;
    int orig = (t < NB) ? g_bsum[t] : 0;
    sh[t] = orig;
    __syncthreads();
#pragma unroll
    for (int off = 1; off < SB; off <<= 1) {
        int v = (t >= off) ? sh[t - off] : 0;
        __syncthreads();
        sh[t] += v;
        __syncthreads();
    }
    if (t < NB) g_bsum[t] = sh[t] - orig;
}

__global__ void scan3_kernel() {
    __shared__ int sh[SB];
    int t = threadIdx.x;
    int i = blockIdx.x * SB + t;
    int v = (i < N_NODES) ? g_cnt[i] : 0;
    if (i < N_NODES) g_cnt[i] = 0;   // reset for next run (first run: zero-initialized)
    sh[t] = v;
    __syncthreads();
#pragma unroll
    for (int off = 1; off < SB; off <<= 1) {
        int u = (t >= off) ? sh[t - off] : 0;
        __syncthreads();
        sh[t] += u;
        __syncthreads();
    }
    int excl = sh[t] - v + g_bsum[blockIdx.x];
    if (i < N_NODES) g_rowstart[i] = excl;
    if (i == N_NODES - 1) g_rowstart[N_NODES] = excl + v;
}

// ---------------- K4: fill CSR buckets (atomic-free, 4 edges/thread MLP) ----------------
__global__ void fill_kernel(const int* __restrict__ ei) {
    int tbase = blockIdx.x * blockDim.x + threadIdx.x;
#pragma unroll
    for (int k = 0; k < 4; k++) {
        int e = tbase + k * HIST_STRIDE;
        if (e < E_EDGES) {
            int src = ei[e];
            int dst = ei[E_EDGES + e];
            g_bucket[g_rowstart[dst] + g_rank[e]] = make_int2(src, e);
        }
    }
}

// ---------------- K5: warp-per-node gather — softmax + aggregation, atomic-free --------
__device__ __forceinline__ float4 edge_alpha(int src, float4 ad) {
    float4 as = *(const float4*)&g_asrc[src * HEADS];
    float4 a;
    a.x = as.x + ad.x; a.x = fmaxf(a.x, NEG_SLOPE * a.x);
    a.y = as.y + ad.y; a.y = fmaxf(a.y, NEG_SLOPE * a.y);
    a.z = as.z + ad.z; a.z = fmaxf(a.z, NEG_SLOPE * a.z);
    a.w = as.w + ad.w; a.w = fmaxf(a.w, NEG_SLOPE * a.w);
    return a;
}

#define GW 8   // warps per block
__global__ void gather_kernel(const float* __restrict__ bias,
                              float* __restrict__ out,
                              float* __restrict__ alpha_out) {
    __shared__ float4 s_al[GW][32];
    __shared__ int    s_src[GW][32];

    const int lane = threadIdx.x & 31;
    const int w    = threadIdx.x >> 5;
    const int node = blockIdx.x * GW + w;
    if (node >= N_NODES) return;

    const int start = g_rowstart[node];
    const int end   = g_rowstart[node + 1];
    const int deg   = end - start;
    const int head  = lane >> 3;

    float4 acc = *(const float4*)&bias[lane * 4];

#define ACCUM_CHUNK(cnt)                                                          \
    do {                                                                          \
        int j = 0;                                                                \
        for (; j + 4 <= (cnt); j += 4) {                                          \
            int   s0 = s_src[w][j+0], s1 = s_src[w][j+1];                         \
            int   s2 = s_src[w][j+2], s3 = s_src[w][j+3];                         \
            float a0 = ((const float*)&s_al[w][j+0])[head];                       \
            float a1 = ((const float*)&s_al[w][j+1])[head];                       \
            float a2 = ((const float*)&s_al[w][j+2])[head];                       \
            float a3 = ((const float*)&s_al[w][j+3])[head];                       \
            float4 h0 = *(const float4*)&g_h[s0 * C_DIM + lane * 4];              \
            float4 h1 = *(const float4*)&g_h[s1 * C_DIM + lane * 4];              \
            float4 h2 = *(const float4*)&g_h[s2 * C_DIM + lane * 4];              \
            float4 h3 = *(const float4*)&g_h[s3 * C_DIM + lane * 4];              \
            acc.x = fmaf(h0.x, a0, acc.x); acc.y = fmaf(h0.y, a0, acc.y);         \
            acc.z = fmaf(h0.z, a0, acc.z); acc.w = fmaf(h0.w, a0, acc.w);         \
            acc.x = fmaf(h1.x, a1, acc.x); acc.y = fmaf(h1.y, a1, acc.y);         \
            acc.z = fmaf(h1.z, a1, acc.z); acc.w = fmaf(h1.w, a1, acc.w);         \
            acc.x = fmaf(h2.x, a2, acc.x); acc.y = fmaf(h2.y, a2, acc.y);         \
            acc.z = fmaf(h2.z, a2, acc.z); acc.w = fmaf(h2.w, a2, acc.w);         \
            acc.x = fmaf(h3.x, a3, acc.x); acc.y = fmaf(h3.y, a3, acc.y);         \
            acc.z = fmaf(h3.z, a3, acc.z); acc.w = fmaf(h3.w, a3, acc.w);         \
        }                                                                         \
        for (; j < (cnt); j++) {                                                  \
            int   sj = s_src[w][j];                                               \
            float aj = ((const float*)&s_al[w][j])[head];                         \
            float4 hv = *(const float4*)&g_h[sj * C_DIM + lane * 4];              \
            acc.x = fmaf(hv.x, aj, acc.x); acc.y = fmaf(hv.y, aj, acc.y);         \
            acc.z = fmaf(hv.z, aj, acc.z); acc.w = fmaf(hv.w, aj, acc.w);         \
        }                                                                         \
    } while (0)

    if (deg > 0 && deg <= 32) {
        float4 ad = *(const float4*)&g_adst[node * HEADS];
        int idx = start + lane;
        bool valid = idx < end;
        int2 be = make_int2(0, 0);
        float4 a = make_float4(NEG_INF_F, NEG_INF_F, NEG_INF_F, NEG_INF_F);
        if (valid) {
            be = g_bucket[idx];
            a = edge_alpha(be.x, ad);
        }
        float4 m = a;
#pragma unroll
        for (int off = 16; off; off >>= 1) {
            m.x = fmaxf(m.x, __shfl_xor_sync(0xffffffffu, m.x, off));
            m.y = fmaxf(m.y, __shfl_xor_sync(0xffffffffu, m.y, off));
            m.z = fmaxf(m.z, __shfl_xor_sync(0xffffffffu, m.z, off));
            m.w = fmaxf(m.w, __shfl_xor_sync(0xffffffffu, m.w, off));
        }
        float4 e = make_float4(0.f, 0.f, 0.f, 0.f);
        if (valid) {
            e.x = __expf(a.x - m.x); e.y = __expf(a.y - m.y);
            e.z = __expf(a.z - m.z); e.w = __expf(a.w - m.w);
        }
        float4 s = e;
#pragma unroll
        for (int off = 16; off; off >>= 1) {
            s.x += __shfl_xor_sync(0xffffffffu, s.x, off);
            s.y += __shfl_xor_sync(0xffffffffu, s.y, off);
            s.z += __shfl_xor_sync(0xffffffffu, s.z, off);
            s.w += __shfl_xor_sync(0xffffffffu, s.w, off);
        }
        float4 al;
        al.x = e.x / (s.x + EPS_F); al.y = e.y / (s.y + EPS_F);
        al.z = e.z / (s.z + EPS_F); al.w = e.w / (s.w + EPS_F);
        if (valid) {
            alpha_out[be.y] = 0.25f * (al.x + al.y + al.z + al.w);
            s_al[w][lane]  = al;
            s_src[w][lane] = be.x;
        }
        __syncwarp();
        ACCUM_CHUNK(deg);
    } else if (deg > 32) {
        float4 ad = *(const float4*)&g_adst[node * HEADS];
        float4 m = make_float4(NEG_INF_F, NEG_INF_F, NEG_INF_F, NEG_INF_F);
        float4 s = make_float4(0.f, 0.f, 0.f, 0.f);
        for (int idx = start + lane; idx < end; idx += 32) {
            int2 be = g_bucket[idx];
            float4 a = edge_alpha(be.x, ad);
            float4 nm;
            nm.x = fmaxf(m.x, a.x); nm.y = fmaxf(m.y, a.y);
            nm.z = fmaxf(m.z, a.z); nm.w = fmaxf(m.w, a.w);
            s.x = s.x * __expf(m.x - nm.x) + __expf(a.x - nm.x);
            s.y = s.y * __expf(m.y - nm.y) + __expf(a.y - nm.y);
            s.z = s.z * __expf(m.z - nm.z) + __expf(a.z - nm.z);
            s.w = s.w * __expf(m.w - nm.w) + __expf(a.w - nm.w);
            m = nm;
        }
#pragma unroll
        for (int off = 16; off; off >>= 1) {
            float4 mo, so;
            mo.x = __shfl_xor_sync(0xffffffffu, m.x, off);
            mo.y = __shfl_xor_sync(0xffffffffu, m.y, off);
            mo.z = __shfl_xor_sync(0xffffffffu, m.z, off);
            mo.w = __shfl_xor_sync(0xffffffffu, m.w, off);
            so.x = __shfl_xor_sync(0xffffffffu, s.x, off);
            so.y = __shfl_xor_sync(0xffffffffu, s.y, off);
            so.z = __shfl_xor_sync(0xffffffffu, s.z, off);
            so.w = __shfl_xor_sync(0xffffffffu, s.w, off);
            float4 nm;
            nm.x = fmaxf(m.x, mo.x); nm.y = fmaxf(m.y, mo.y);
            nm.z = fmaxf(m.z, mo.z); nm.w = fmaxf(m.w, mo.w);
            s.x = s.x * __expf(m.x - nm.x) + so.x * __expf(mo.x - nm.x);
            s.y = s.y * __expf(m.y - nm.y) + so.y * __expf(mo.y - nm.y);
            s.z = s.z * __expf(m.z - nm.z) + so.z * __expf(mo.z - nm.z);
            s.w = s.w * __expf(m.w - nm.w) + so.w * __expf(mo.w - nm.w);
            m = nm;
        }
        float4 inv;
        inv.x = 1.0f / (s.x + EPS_F); inv.y = 1.0f / (s.y + EPS_F);
        inv.z = 1.0f / (s.z + EPS_F); inv.w = 1.0f / (s.w + EPS_F);

        for (int base = start; base < end; base += 32) {
            int idx = base + lane;
            if (idx < end) {
                int2 be = g_bucket[idx];
                float4 a = edge_alpha(be.x, ad);
                float4 al;
                al.x = __expf(a.x - m.x) * inv.x;
                al.y = __expf(a.y - m.y) * inv.y;
                al.z = __expf(a.z - m.z) * inv.z;
                al.w = __expf(a.w - m.w) * inv.w;
                alpha_out[be.y] = 0.25f * (al.x + al.y + al.z + al.w);
                s_al[w][lane]  = al;
                s_src[w][lane] = be.x;
            }
            __syncwarp();
            int cnt = min(32, end - base);
            ACCUM_CHUNK(cnt);
            __syncwarp();
        }
    }

    *(float4*)&out[node * C_DIM + lane * 4] = acc;
#undef ACCUM_CHUNK
}

// ---------------- launch ----------------
extern "C" void kernel_launch(void* const* d_in, const int* in_sizes, int n_in,
                              void* d_out, int out_size) {
    const float* x       = (const float*)d_in[0];
    const int*   ei      = (const int*)d_in[1];     // edge_index is int32
    const float* W       = (const float*)d_in[2];
    const float* att_src = (const float*)d_in[3];
    const float* att_dst = (const float*)d_in[4];
    const float* bias    = (const float*)d_in[5];
    (void)in_sizes; (void)n_in; (void)out_size;

    float* out       = (float*)d_out;
    float* alpha_out = out + (size_t)N_NODES * C_DIM;

    cudaFuncSetAttribute(gemm_hist_kernel,
                         cudaFuncAttributeMaxDynamicSharedMemorySize, GEMM_SMEM_BYTES);

    gemm_hist_kernel<<<GEMM_BLOCKS + HIST_BLOCKS, 256, GEMM_SMEM_BYTES>>>(
        x, W, att_src, att_dst, ei);
    scan1_kernel<<<NB, SB>>>();
    scan2_kernel<<<1, SB>>>();
    scan3_kernel<<<NB, SB>>>();
    fill_kernel<<<HIST_BLOCKS, 256>>>(ei);
    gather_kernel<<<(N_NODES + GW - 1) / GW, GW * 32>>>(bias, out, alpha_out);
}

// round 16
// speedup vs baseline: 1.0546x; 1.0314x over previous
#include <cuda_runtime.h>
#include <cstdint>

#define N_NODES 50000
#define E_EDGES 800000
#define IN_DIM  128
#define HEADS   4
#define OUT_DIM 32
#define C_DIM   128   // HEADS*OUT_DIM
#define NEG_SLOPE 0.2f
#define EPS_F 1e-16f
#define NEG_INF_F -3.402823e38f

#define SB 256
#define NB ((N_NODES + SB - 1) / SB)   // 196 scan blocks

#define EDGE_THREADS ((E_EDGES + 3) / 4)             // 200000 (4 edges/thread)
#define EDGE_BLOCKS ((EDGE_THREADS + 255) / 256)     // 782
#define EDGE_STRIDE (EDGE_BLOCKS * 256)              // 200192

// ---------------- scratch (device globals; no runtime allocation) ----------------
__device__ __align__(16) float g_h[N_NODES * C_DIM];      // 25.6 MB: h = x @ W^T
__device__ __align__(16) float g_asrc[N_NODES * HEADS];   // per-node src scores
__device__ __align__(16) float g_adst[N_NODES * HEADS];   // per-node dst scores
__device__ __align__(16) int   g_cnt[N_NODES];            // dst histogram (zeroed by scan23)
__device__ __align__(16) int   g_rank[E_EDGES];           // edge rank within its dst bucket
__device__ __align__(16) int   g_rowstart[N_NODES + 1];   // CSR row offsets
__device__ __align__(16) int   g_bsum[NB];                // scan block sums (unscanned)
__device__ __align__(16) int2  g_bucket[E_EDGES];         // per-dst edge list: (src, edge_id)

// ================= K1: tf32 mma.sync GEMM + per-node attention scores =================
#define GP 132   // smem pitch in words (128+4: quad LDS pattern conflict-free)
#define GEMM_SMEM_WORDS (2 * 128 * GP + 256)
#define GEMM_SMEM_BYTES (GEMM_SMEM_WORDS * 4)

__device__ __forceinline__ uint32_t f2tf32(float f) {
    uint32_t r;
    asm("cvt.rna.tf32.f32 %0, %1;" : "=r"(r) : "f"(f));
    return r;
}
__device__ __forceinline__ void mma_tf32(float d[4], uint32_t a0, uint32_t a1,
                                         uint32_t a2, uint32_t a3,
                                         uint32_t b0, uint32_t b1) {
    asm volatile(
        "mma.sync.aligned.m16n8k8.row.col.f32.tf32.tf32.f32 "
        "{%0,%1,%2,%3}, {%4,%5,%6,%7}, {%8,%9}, {%0,%1,%2,%3};"
        : "+f"(d[0]), "+f"(d[1]), "+f"(d[2]), "+f"(d[3])
        : "r"(a0), "r"(a1), "r"(a2), "r"(a3), "r"(b0), "r"(b1));
}

__global__ __launch_bounds__(256, 1) void gemm_mma_kernel(const float* __restrict__ x,
                                                          const float* __restrict__ W,
                                                          const float* __restrict__ att_src,
                                                          const float* __restrict__ att_dst) {
    extern __shared__ uint32_t smem[];
    uint32_t* xs    = smem;                 // [128][GP] tf32 bits
    uint32_t* ws    = smem + 128 * GP;      // [128][GP] tf32 bits
    float*    s_att = (float*)(smem + 2 * 128 * GP);   // [256] = att_src | att_dst

    const int tid  = threadIdx.x;
    const int wid  = tid >> 5;
    const int lane = tid & 31;
    const int row0 = blockIdx.x * 128;

    s_att[tid] = (tid < 128) ? att_src[tid] : att_dst[tid - 128];

    for (int idx = tid; idx < 4096; idx += 256) {
        int r = idx >> 5, q = idx & 31;
        float4 wv = *(const float4*)&W[r * IN_DIM + q * 4];
        uint32_t* wp = &ws[r * GP + q * 4];
        wp[0] = f2tf32(wv.x); wp[1] = f2tf32(wv.y);
        wp[2] = f2tf32(wv.z); wp[3] = f2tf32(wv.w);

        int m = row0 + r;
        float4 xv = make_float4(0.f, 0.f, 0.f, 0.f);
        if (m < N_NODES) xv = *(const float4*)&x[m * IN_DIM + q * 4];
        uint32_t* xp = &xs[r * GP + q * 4];
        xp[0] = f2tf32(xv.x); xp[1] = f2tf32(xv.y);
        xp[2] = f2tf32(xv.z); xp[3] = f2tf32(xv.w);
    }
    __syncthreads();

    const int g  = lane >> 2;   // group id (row within fragment)
    const int t4 = lane & 3;

    float acc[16][4];
#pragma unroll
    for (int n = 0; n < 16; n++)
#pragma unroll
        for (int j = 0; j < 4; j++) acc[n][j] = 0.0f;

    const int arow = wid * 16 + g;
#pragma unroll 1
    for (int ks = 0; ks < 16; ks++) {
        int kc = ks * 8 + t4;
        uint32_t a0 = xs[arow * GP + kc];
        uint32_t a1 = xs[(arow + 8) * GP + kc];
        uint32_t a2 = xs[arow * GP + kc + 4];
        uint32_t a3 = xs[(arow + 8) * GP + kc + 4];
#pragma unroll
        for (int n = 0; n < 16; n++) {
            uint32_t b0 = ws[(n * 8 + g) * GP + kc];
            uint32_t b1 = ws[(n * 8 + g) * GP + kc + 4];
            mma_tf32(acc[n], a0, a1, a2, a3, b0, b1);
        }
    }

    // epilogue: store h rows r0 & r1, fold attention dot products
    const int r0 = row0 + wid * 16 + g;
    const int r1 = r0 + 8;
    float vs0[HEADS], vd0[HEADS], vs1[HEADS], vd1[HEADS];
#pragma unroll
    for (int h = 0; h < HEADS; h++) { vs0[h] = vd0[h] = vs1[h] = vd1[h] = 0.f; }

#pragma unroll
    for (int n = 0; n < 16; n++) {
        int c0 = n * 8 + t4 * 2;
        int c1 = c0 + 1;
        int h  = n >> 2;   // head = c0 >> 5
        if (r0 < N_NODES)
            *(float2*)&g_h[(size_t)r0 * C_DIM + c0] = make_float2(acc[n][0], acc[n][1]);
        if (r1 < N_NODES)
            *(float2*)&g_h[(size_t)r1 * C_DIM + c0] = make_float2(acc[n][2], acc[n][3]);
        vs0[h] += acc[n][0] * s_att[c0]       + acc[n][1] * s_att[c1];
        vd0[h] += acc[n][0] * s_att[128 + c0] + acc[n][1] * s_att[128 + c1];
        vs1[h] += acc[n][2] * s_att[c0]       + acc[n][3] * s_att[c1];
        vd1[h] += acc[n][2] * s_att[128 + c0] + acc[n][3] * s_att[128 + c1];
    }
#pragma unroll
    for (int h = 0; h < HEADS; h++) {
        vs0[h] += __shfl_xor_sync(0xffffffffu, vs0[h], 1);
        vs0[h] += __shfl_xor_sync(0xffffffffu, vs0[h], 2);
        vd0[h] += __shfl_xor_sync(0xffffffffu, vd0[h], 1);
        vd0[h] += __shfl_xor_sync(0xffffffffu, vd0[h], 2);
        vs1[h] += __shfl_xor_sync(0xffffffffu, vs1[h], 1);
        vs1[h] += __shfl_xor_sync(0xffffffffu, vs1[h], 2);
        vd1[h] += __shfl_xor_sync(0xffffffffu, vd1[h], 1);
        vd1[h] += __shfl_xor_sync(0xffffffffu, vd1[h], 2);
    }
    if (t4 == 0) {
        if (r0 < N_NODES) {
#pragma unroll
            for (int h = 0; h < HEADS; h++) {
                g_asrc[r0 * HEADS + h] = vs0[h];
                g_adst[r0 * HEADS + h] = vd0[h];
            }
        }
        if (r1 < N_NODES) {
#pragma unroll
            for (int h = 0; h < HEADS; h++) {
                g_asrc[r1 * HEADS + h] = vs1[h];
                g_adst[r1 * HEADS + h] = vd1[h];
            }
        }
    }
}

// ---------------- K2: dst histogram + per-edge rank (MLP-4, no smem, full occ) ---------
__global__ void hist_kernel(const int* __restrict__ ei) {
    int tbase = blockIdx.x * blockDim.x + threadIdx.x;
    int e0 = tbase;
    int e1 = tbase + EDGE_STRIDE;
    int e2 = tbase + 2 * EDGE_STRIDE;
    int e3 = tbase + 3 * EDGE_STRIDE;
    int d0 = (e0 < E_EDGES) ? ei[E_EDGES + e0] : 0;
    int d1 = (e1 < E_EDGES) ? ei[E_EDGES + e1] : 0;
    int d2 = (e2 < E_EDGES) ? ei[E_EDGES + e2] : 0;
    int d3 = (e3 < E_EDGES) ? ei[E_EDGES + e3] : 0;
    if (e0 < E_EDGES) g_rank[e0] = atomicAdd(&g_cnt[d0], 1);
    if (e1 < E_EDGES) g_rank[e1] = atomicAdd(&g_cnt[d1], 1);
    if (e2 < E_EDGES) g_rank[e2] = atomicAdd(&g_cnt[d2], 1);
    if (e3 < E_EDGES) g_rank[e3] = atomicAdd(&g_cnt[d3], 1);
}

// ---------------- K3a: per-block sums of g_cnt ----------------
__global__ void scan1_kernel() {
    __shared__ int sh[SB];
    int t = threadIdx.x;
    int i = blockIdx.x * SB + t;
    sh[t] = (i < N_NODES) ? g_cnt[i] : 0;
    __syncthreads();
#pragma unroll
    for (int off = SB / 2; off; off >>= 1) {
        if (t < off) sh[t] += sh[t + off];
        __syncthreads();
    }
    if (t == 0) g_bsum[blockIdx.x] = sh[0];
}

// ---------------- K3b: final scan (folds block-prefix reduce of g_bsum) ----------------
__global__ void scan23_kernel() {
    __shared__ int sh[SB];
    __shared__ int shp[SB];
    const int t   = threadIdx.x;
    const int bid = blockIdx.x;
    const int i   = bid * SB + t;

    // block prefix: sum of g_bsum[j] for j < bid (NB=196 <= SB)
    shp[t] = (t < bid && t < NB) ? g_bsum[t] : 0;

    int v = (i < N_NODES) ? g_cnt[i] : 0;
    if (i < N_NODES) g_cnt[i] = 0;   // reset for next graph replay
    sh[t] = v;
    __syncthreads();
#pragma unroll
    for (int off = SB / 2; off; off >>= 1) {
        if (t < off) shp[t] += shp[t + off];
        __syncthreads();
    }
    const int bprefix = shp[0];   // stable: only read after the reduce barrier
    __syncthreads();
#pragma unroll
    for (int off = 1; off < SB; off <<= 1) {
        int u = (t >= off) ? sh[t - off] : 0;
        __syncthreads();
        sh[t] += u;
        __syncthreads();
    }
    int excl = sh[t] - v + bprefix;
    if (i < N_NODES) g_rowstart[i] = excl;
    if (i == N_NODES - 1) g_rowstart[N_NODES] = excl + v;
}

// ---------------- K4: fill CSR buckets (atomic-free, MLP-4) ----------------
__global__ void fill_kernel(const int* __restrict__ ei) {
    int tbase = blockIdx.x * blockDim.x + threadIdx.x;
#pragma unroll
    for (int k = 0; k < 4; k++) {
        int e = tbase + k * EDGE_STRIDE;
        if (e < E_EDGES) {
            int src = ei[e];
            int dst = ei[E_EDGES + e];
            g_bucket[g_rowstart[dst] + g_rank[e]] = make_int2(src, e);
        }
    }
}

// ---------------- K5: warp-per-node gather — softmax + aggregation, atomic-free --------
__device__ __forceinline__ float4 edge_alpha(int src, float4 ad) {
    float4 as = *(const float4*)&g_asrc[src * HEADS];
    float4 a;
    a.x = as.x + ad.x; a.x = fmaxf(a.x, NEG_SLOPE * a.x);
    a.y = as.y + ad.y; a.y = fmaxf(a.y, NEG_SLOPE * a.y);
    a.z = as.z + ad.z; a.z = fmaxf(a.z, NEG_SLOPE * a.z);
    a.w = as.w + ad.w; a.w = fmaxf(a.w, NEG_SLOPE * a.w);
    return a;
}

#define GW 8   // warps per block
__global__ void gather_kernel(const float* __restrict__ bias,
                              float* __restrict__ out,
                              float* __restrict__ alpha_out) {
    __shared__ float4 s_al[GW][32];
    __shared__ int    s_src[GW][32];

    const int lane = threadIdx.x & 31;
    const int w    = threadIdx.x >> 5;
    const int node = blockIdx.x * GW + w;
    if (node >= N_NODES) return;

    const int start = g_rowstart[node];
    const int end   = g_rowstart[node + 1];
    const int deg   = end - start;
    const int head  = lane >> 3;

    float4 acc = *(const float4*)&bias[lane * 4];

#define ACCUM_CHUNK(cnt)                                                          \
    do {                                                                          \
        int j = 0;                                                                \
        for (; j + 4 <= (cnt); j += 4) {                                          \
            int   s0 = s_src[w][j+0], s1 = s_src[w][j+1];                         \
            int   s2 = s_src[w][j+2], s3 = s_src[w][j+3];                         \
            float a0 = ((const float*)&s_al[w][j+0])[head];                       \
            float a1 = ((const float*)&s_al[w][j+1])[head];                       \
            float a2 = ((const float*)&s_al[w][j+2])[head];                       \
            float a3 = ((const float*)&s_al[w][j+3])[head];                       \
            float4 h0 = *(const float4*)&g_h[s0 * C_DIM + lane * 4];              \
            float4 h1 = *(const float4*)&g_h[s1 * C_DIM + lane * 4];              \
            float4 h2 = *(const float4*)&g_h[s2 * C_DIM + lane * 4];              \
            float4 h3 = *(const float4*)&g_h[s3 * C_DIM + lane * 4];              \
            acc.x = fmaf(h0.x, a0, acc.x); acc.y = fmaf(h0.y, a0, acc.y);         \
            acc.z = fmaf(h0.z, a0, acc.z); acc.w = fmaf(h0.w, a0, acc.w);         \
            acc.x = fmaf(h1.x, a1, acc.x); acc.y = fmaf(h1.y, a1, acc.y);         \
            acc.z = fmaf(h1.z, a1, acc.z); acc.w = fmaf(h1.w, a1, acc.w);         \
            acc.x = fmaf(h2.x, a2, acc.x); acc.y = fmaf(h2.y, a2, acc.y);         \
            acc.z = fmaf(h2.z, a2, acc.z); acc.w = fmaf(h2.w, a2, acc.w);         \
            acc.x = fmaf(h3.x, a3, acc.x); acc.y = fmaf(h3.y, a3, acc.y);         \
            acc.z = fmaf(h3.z, a3, acc.z); acc.w = fmaf(h3.w, a3, acc.w);         \
        }                                                                         \
        for (; j < (cnt); j++) {                                                  \
            int   sj = s_src[w][j];                                               \
            float aj = ((const float*)&s_al[w][j])[head];                         \
            float4 hv = *(const float4*)&g_h[sj * C_DIM + lane * 4];              \
            acc.x = fmaf(hv.x, aj, acc.x); acc.y = fmaf(hv.y, aj, acc.y);         \
            acc.z = fmaf(hv.z, aj, acc.z); acc.w = fmaf(hv.w, aj, acc.w);         \
        }                                                                         \
    } while (0)

    if (deg > 0 && deg <= 32) {
        float4 ad = *(const float4*)&g_adst[node * HEADS];
        int idx = start + lane;
        bool valid = idx < end;
        int2 be = make_int2(0, 0);
        float4 a = make_float4(NEG_INF_F, NEG_INF_F, NEG_INF_F, NEG_INF_F);
        if (valid) {
            be = g_bucket[idx];
            a = edge_alpha(be.x, ad);
        }
        float4 m = a;
#pragma unroll
        for (int off = 16; off; off >>= 1) {
            m.x = fmaxf(m.x, __shfl_xor_sync(0xffffffffu, m.x, off));
            m.y = fmaxf(m.y, __shfl_xor_sync(0xffffffffu, m.y, off));
            m.z = fmaxf(m.z, __shfl_xor_sync(0xffffffffu, m.z, off));
            m.w = fmaxf(m.w, __shfl_xor_sync(0xffffffffu, m.w, off));
        }
        float4 e = make_float4(0.f, 0.f, 0.f, 0.f);
        if (valid) {
            e.x = __expf(a.x - m.x); e.y = __expf(a.y - m.y);
            e.z = __expf(a.z - m.z); e.w = __expf(a.w - m.w);
        }
        float4 s = e;
#pragma unroll
        for (int off = 16; off; off >>= 1) {
            s.x += __shfl_xor_sync(0xffffffffu, s.x, off);
            s.y += __shfl_xor_sync(0xffffffffu, s.y, off);
            s.z += __shfl_xor_sync(0xffffffffu, s.z, off);
            s.w += __shfl_xor_sync(0xffffffffu, s.w, off);
        }
        float4 al;
        al.x = e.x / (s.x + EPS_F); al.y = e.y / (s.y + EPS_F);
        al.z = e.z / (s.z + EPS_F); al.w = e.w / (s.w + EPS_F);
        if (valid) {
            alpha_out[be.y] = 0.25f * (al.x + al.y + al.z + al.w);
            s_al[w][lane]  = al;
            s_src[w][lane] = be.x;
        }
        __syncwarp();
        ACCUM_CHUNK(deg);
    } else if (deg > 32) {
        float4 ad = *(const float4*)&g_adst[node * HEADS];
        float4 m = make_float4(NEG_INF_F, NEG_INF_F, NEG_INF_F, NEG_INF_F);
        float4 s = make_float4(0.f, 0.f, 0.f, 0.f);
        for (int idx = start + lane; idx < end; idx += 32) {
            int2 be = g_bucket[idx];
            float4 a = edge_alpha(be.x, ad);
            float4 nm;
            nm.x = fmaxf(m.x, a.x); nm.y = fmaxf(m.y, a.y);
            nm.z = fmaxf(m.z, a.z); nm.w = fmaxf(m.w, a.w);
            s.x = s.x * __expf(m.x - nm.x) + __expf(a.x - nm.x);
            s.y = s.y * __expf(m.y - nm.y) + __expf(a.y - nm.y);
            s.z = s.z * __expf(m.z - nm.z) + __expf(a.z - nm.z);
            s.w = s.w * __expf(m.w - nm.w) + __expf(a.w - nm.w);
            m = nm;
        }
#pragma unroll
        for (int off = 16; off; off >>= 1) {
            float4 mo, so;
            mo.x = __shfl_xor_sync(0xffffffffu, m.x, off);
            mo.y = __shfl_xor_sync(0xffffffffu, m.y, off);
            mo.z = __shfl_xor_sync(0xffffffffu, m.z, off);
            mo.w = __shfl_xor_sync(0xffffffffu, m.w, off);
            so.x = __shfl_xor_sync(0xffffffffu, s.x, off);
            so.y = __shfl_xor_sync(0xffffffffu, s.y, off);
            so.z = __shfl_xor_sync(0xffffffffu, s.z, off);
            so.w = __shfl_xor_sync(0xffffffffu, s.w, off);
            float4 nm;
            nm.x = fmaxf(m.x, mo.x); nm.y = fmaxf(m.y, mo.y);
            nm.z = fmaxf(m.z, mo.z); nm.w = fmaxf(m.w, mo.w);
            s.x = s.x * __expf(m.x - nm.x) + so.x * __expf(mo.x - nm.x);
            s.y = s.y * __expf(m.y - nm.y) + so.y * __expf(mo.y - nm.y);
            s.z = s.z * __expf(m.z - nm.z) + so.z * __expf(mo.z - nm.z);
            s.w = s.w * __expf(m.w - nm.w) + so.w * __expf(mo.w - nm.w);
            m = nm;
        }
        float4 inv;
        inv.x = 1.0f / (s.x + EPS_F); inv.y = 1.0f / (s.y + EPS_F);
        inv.z = 1.0f / (s.z + EPS_F); inv.w = 1.0f / (s.w + EPS_F);

        for (int base = start; base < end; base += 32) {
            int idx = base + lane;
            if (idx < end) {
                int2 be = g_bucket[idx];
                float4 a = edge_alpha(be.x, ad);
                float4 al;
                al.x = __expf(a.x - m.x) * inv.x;
                al.y = __expf(a.y - m.y) * inv.y;
                al.z = __expf(a.z - m.z) * inv.z;
                al.w = __expf(a.w - m.w) * inv.w;
                alpha_out[be.y] = 0.25f * (al.x + al.y + al.z + al.w);
                s_al[w][lane]  = al;
                s_src[w][lane] = be.x;
            }
            __syncwarp();
            int cnt = min(32, end - base);
            ACCUM_CHUNK(cnt);
            __syncwarp();
        }
    }

    *(float4*)&out[node * C_DIM + lane * 4] = acc;
#undef ACCUM_CHUNK
}

// ---------------- launch ----------------
extern "C" void kernel_launch(void* const* d_in, const int* in_sizes, int n_in,
                              void* d_out, int out_size) {
    const float* x       = (const float*)d_in[0];
    const int*   ei      = (const int*)d_in[1];     // edge_index is int32
    const float* W       = (const float*)d_in[2];
    const float* att_src = (const float*)d_in[3];
    const float* att_dst = (const float*)d_in[4];
    const float* bias    = (const float*)d_in[5];
    (void)in_sizes; (void)n_in; (void)out_size;

    float* out       = (float*)d_out;
    float* alpha_out = out + (size_t)N_NODES * C_DIM;

    cudaFuncSetAttribute(gemm_mma_kernel,
                         cudaFuncAttributeMaxDynamicSharedMemorySize, GEMM_SMEM_BYTES);

    gemm_mma_kernel<<<(N_NODES + 127) / 128, 256, GEMM_SMEM_BYTES>>>(x, W, att_src, att_dst);
    hist_kernel<<<EDGE_BLOCKS, 256>>>(ei);
    scan1_kernel<<<NB, SB>>>();
    scan23_kernel<<<NB, SB>>>();
    fill_kernel<<<EDGE_BLOCKS, 256>>>(ei);
    gather_kernel<<<(N_NODES + GW - 1) / GW, GW * 32>>>(bias, out, alpha_out);
}